// round 16
// baseline (speedup 1.0000x reference)
#include <cuda_runtime.h>
#include <math.h>
#include <stdint.h>

#define Bq 2
#define Lq 2048
#define Dq 768
#define Hq 12
#define ROWS (Bq*Lq)   /* 4096 */

// ---------------- scratch (device globals; no allocation allowed) ----------------
__device__ float g_t1[(size_t)ROWS*3072];
__device__ float g_p [(size_t)ROWS*1024];
__device__ float g_ha[(size_t)ROWS*Dq];
__device__ float g_hb[(size_t)ROWS*Dq];
__device__ float g_x [(size_t)ROWS*Dq];
__device__ float g_qk[(size_t)ROWS*Dq];
__device__ float g_q [(size_t)ROWS*Dq];
__device__ float g_k [(size_t)ROWS*Dq];
__device__ float g_v [(size_t)ROWS*Dq];
__device__ float g_att[(size_t)ROWS*Dq];
__device__ float g_o [(size_t)ROWS*Dq];
__device__ float g_x2[(size_t)ROWS*Dq];
__device__ float g_wr[18524160];   // pre-rounded weights (74MB), contiguous

__device__ __forceinline__ float gelu_f(float x){
    return 0.5f*x*(1.0f+erff(x*0.70710678118654752440f));
}
__device__ __forceinline__ uint32_t tf32u(float x){
    uint32_t u;
    asm("cvt.rna.tf32.f32 %0, %1;" : "=r"(u) : "f"(x));
    return u;
}
__device__ __forceinline__ float tf32r(float x){
    return __uint_as_float(tf32u(x));
}
__device__ __forceinline__ void cp16(uint32_t smem_dst, const void* gsrc){
    asm volatile("cp.async.ca.shared.global [%0], [%1], 16;\n"
                 :: "r"(smem_dst), "l"(gsrc));
}

// ---------------- merged tf32 round-copy of all 12 weight matrices ----------------
struct WSrc { const float4* s[12]; };
#define W_TOTAL4 4631040
__global__ void round_all(WSrc w, float4* __restrict__ dst)
{
    const int end4[12] = {589824, 1179648, 1769472, 1780224, 2075136, 2861568,
                          3009024, 3156480, 3303936, 3451392, 4041216, 4631040};
    int i = blockIdx.x * blockDim.x + threadIdx.x;
    if (i >= W_TOTAL4) return;
    int s = 0;
    #pragma unroll
    for (int k = 0; k < 12; k++) if (i >= end4[k]) s = k + 1;
    int st = (s == 0) ? 0 : end4[s-1];
    float4 v = w.s[s][i - st];
    dst[i] = make_float4(tf32r(v.x), tf32r(v.y), tf32r(v.z), tf32r(v.w));
}

// ---------------- tensor-core TF32 GEMM body, 2-stage cp.async pipeline (R9)
#define GEMM_SMEM (2*(128*36 + 32*136)*4)
template<int GELU, int RES, int CVTA, int ROUT>
__device__ __forceinline__ void gemm_body(
    const float* __restrict__ A, const float* __restrict__ Bm,
    const float* __restrict__ bias, const float* __restrict__ Rr,
    float* __restrict__ C, int N, int K)
{
    extern __shared__ uint32_t smem_u[];
    uint32_t* AsB = smem_u;
    uint32_t* BsB = smem_u + 2*128*36;
    const int tid  = threadIdx.x;
    const int warp = tid >> 5, lane = tid & 31;
    const int g = lane >> 2, tc = lane & 3;
    const int wm0 = (warp & 1) * 64, wn0 = (warp >> 1) * 32;
    const int row0 = blockIdx.y * 128, col0 = blockIdx.x * 128;
    const bool colFull = (col0 + 128 <= N);

    float acc[4][4][4] = {};
    const int ar = tid >> 3,  ac = (tid & 7) * 4;
    const int bk = tid >> 5,  bc = (tid & 31) * 4;
    const int nt = K / 32;

    auto issue = [&](int kt, int s){
        uint32_t* as = AsB + s * (128*36);
        uint32_t* bs = BsB + s * (32*136);
        const int k0 = kt * 32;
        #pragma unroll
        for (int p = 0; p < 4; p++) {
            int r = ar + p * 32;
            cp16((uint32_t)__cvta_generic_to_shared(&as[r*36 + ac]),
                 A + (size_t)(row0 + r) * K + k0 + ac);
        }
        if (colFull) {
            #pragma unroll
            for (int p = 0; p < 4; p++) {
                int kr = bk + p * 8;
                cp16((uint32_t)__cvta_generic_to_shared(&bs[kr*136 + bc]),
                     Bm + (size_t)(k0 + kr) * N + col0 + bc);
            }
        } else {
            #pragma unroll
            for (int p = 0; p < 4; p++) {
                int kr = bk + p * 8;
                #pragma unroll
                for (int u = 0; u < 4; u++) {
                    int c = col0 + bc + u;
                    bs[kr*136 + bc + u] =
                        (c < N) ? __float_as_uint(Bm[(size_t)(k0 + kr) * N + c]) : 0u;
                }
            }
        }
        asm volatile("cp.async.commit_group;\n");
    };

    issue(0, 0);
    for (int kt = 0; kt < nt; kt++) {
        const int cur = kt & 1;
        if (kt + 1 < nt) {
            issue(kt + 1, cur ^ 1);
            asm volatile("cp.async.wait_group 1;\n");
        } else {
            asm volatile("cp.async.wait_group 0;\n");
        }
        __syncthreads();
        const uint32_t* as = AsB + cur * (128*36);
        const uint32_t* bs = BsB + cur * (32*136);
        #pragma unroll
        for (int k8 = 0; k8 < 32; k8 += 8) {
            uint32_t af[4][4], bf[4][2];
            #pragma unroll
            for (int mi = 0; mi < 4; mi++) {
                const uint32_t* base = &as[(wm0 + mi*16 + g) * 36 + k8 + tc];
                if (CVTA) {
                    af[mi][0] = tf32u(__uint_as_float(base[0]));
                    af[mi][1] = tf32u(__uint_as_float(base[8*36]));
                    af[mi][2] = tf32u(__uint_as_float(base[4]));
                    af[mi][3] = tf32u(__uint_as_float(base[8*36 + 4]));
                } else {
                    af[mi][0] = base[0];
                    af[mi][1] = base[8*36];
                    af[mi][2] = base[4];
                    af[mi][3] = base[8*36 + 4];
                }
            }
            #pragma unroll
            for (int ni = 0; ni < 4; ni++) {
                const uint32_t* base = &bs[(k8 + tc) * 136 + wn0 + ni*8 + g];
                bf[ni][0] = base[0];
                bf[ni][1] = base[4*136];
            }
            #pragma unroll
            for (int mi = 0; mi < 4; mi++)
                #pragma unroll
                for (int ni = 0; ni < 4; ni++)
                    asm volatile(
                        "mma.sync.aligned.m16n8k8.row.col.f32.tf32.tf32.f32 "
                        "{%0,%1,%2,%3}, {%4,%5,%6,%7}, {%8,%9}, {%0,%1,%2,%3};"
                        : "+f"(acc[mi][ni][0]), "+f"(acc[mi][ni][1]),
                          "+f"(acc[mi][ni][2]), "+f"(acc[mi][ni][3])
                        : "r"(af[mi][0]), "r"(af[mi][1]), "r"(af[mi][2]), "r"(af[mi][3]),
                          "r"(bf[ni][0]), "r"(bf[ni][1]));
        }
        __syncthreads();
    }

    #pragma unroll
    for (int mi = 0; mi < 4; mi++) {
        int r0 = row0 + wm0 + mi*16 + g;
        #pragma unroll
        for (int ni = 0; ni < 4; ni++) {
            int c = col0 + wn0 + ni*8 + tc*2;
            if (c < N) {
                float b0 = bias[c], b1 = bias[c+1];
                float v0 = acc[mi][ni][0] + b0, v1 = acc[mi][ni][1] + b1;
                float v2 = acc[mi][ni][2] + b0, v3 = acc[mi][ni][3] + b1;
                if (GELU) { v0 = gelu_f(v0); v1 = gelu_f(v1); v2 = gelu_f(v2); v3 = gelu_f(v3); }
                if (ROUT) { v0 = tf32r(v0); v1 = tf32r(v1); v2 = tf32r(v2); v3 = tf32r(v3); }
                if (RES) {
                    v0 += Rr[(size_t)r0*N + c];     v1 += Rr[(size_t)r0*N + c + 1];
                    v2 += Rr[(size_t)(r0+8)*N + c]; v3 += Rr[(size_t)(r0+8)*N + c + 1];
                }
                *(float2*)(C + (size_t)r0*N + c)     = make_float2(v0, v1);
                *(float2*)(C + (size_t)(r0+8)*N + c) = make_float2(v2, v3);
            }
        }
    }
}

template<int GELU, int RES, int CVTA, int ROUT>
__global__ void __launch_bounds__(256, 2) gemm_tc(
    const float* __restrict__ A, const float* __restrict__ Bm,
    const float* __restrict__ bias, const float* __restrict__ Rr,
    float* __restrict__ C, int N, int K)
{
    gemm_body<GELU, RES, CVTA, ROUT>(A, Bm, bias, Rr, C, N, K);
}

// ---------------- split-K TF32 GEMM: C += chunk via atomicAdd (C pre-zeroed)
template<int RES>
__global__ void __launch_bounds__(256, 2) gemm_tc_sk(
    const float* __restrict__ A, const float* __restrict__ Bm,
    const float* __restrict__ bias, const float* __restrict__ Rr,
    float* __restrict__ C, int N, int K, int KC)
{
    extern __shared__ uint32_t smem_u[];
    uint32_t* AsB = smem_u;
    uint32_t* BsB = smem_u + 2*128*36;
    const int tid  = threadIdx.x;
    const int warp = tid >> 5, lane = tid & 31;
    const int g = lane >> 2, tc = lane & 3;
    const int wm0 = (warp & 1) * 64, wn0 = (warp >> 1) * 32;
    const int row0 = blockIdx.y * 128, col0 = blockIdx.x * 128;
    const int z = blockIdx.z;
    const int kbase = z * KC;
    const bool colFull = (col0 + 128 <= N);

    float acc[4][4][4] = {};
    const int ar = tid >> 3,  ac = (tid & 7) * 4;
    const int bk = tid >> 5,  bc = (tid & 31) * 4;
    const int nt = KC / 32;

    auto issue = [&](int kt, int s){
        uint32_t* as = AsB + s * (128*36);
        uint32_t* bs = BsB + s * (32*136);
        const int k0 = kbase + kt * 32;
        #pragma unroll
        for (int p = 0; p < 4; p++) {
            int r = ar + p * 32;
            cp16((uint32_t)__cvta_generic_to_shared(&as[r*36 + ac]),
                 A + (size_t)(row0 + r) * K + k0 + ac);
        }
        if (colFull) {
            #pragma unroll
            for (int p = 0; p < 4; p++) {
                int kr = bk + p * 8;
                cp16((uint32_t)__cvta_generic_to_shared(&bs[kr*136 + bc]),
                     Bm + (size_t)(k0 + kr) * N + col0 + bc);
            }
        } else {
            #pragma unroll
            for (int p = 0; p < 4; p++) {
                int kr = bk + p * 8;
                #pragma unroll
                for (int u = 0; u < 4; u++) {
                    int c = col0 + bc + u;
                    bs[kr*136 + bc + u] =
                        (c < N) ? __float_as_uint(Bm[(size_t)(k0 + kr) * N + c]) : 0u;
                }
            }
        }
        asm volatile("cp.async.commit_group;\n");
    };

    issue(0, 0);
    for (int kt = 0; kt < nt; kt++) {
        const int cur = kt & 1;
        if (kt + 1 < nt) {
            issue(kt + 1, cur ^ 1);
            asm volatile("cp.async.wait_group 1;\n");
        } else {
            asm volatile("cp.async.wait_group 0;\n");
        }
        __syncthreads();
        const uint32_t* as = AsB + cur * (128*36);
        const uint32_t* bs = BsB + cur * (32*136);
        #pragma unroll
        for (int k8 = 0; k8 < 32; k8 += 8) {
            uint32_t af[4][4], bf[4][2];
            #pragma unroll
            for (int mi = 0; mi < 4; mi++) {
                const uint32_t* base = &as[(wm0 + mi*16 + g) * 36 + k8 + tc];
                af[mi][0] = base[0];
                af[mi][1] = base[8*36];
                af[mi][2] = base[4];
                af[mi][3] = base[8*36 + 4];
            }
            #pragma unroll
            for (int ni = 0; ni < 4; ni++) {
                const uint32_t* base = &bs[(k8 + tc) * 136 + wn0 + ni*8 + g];
                bf[ni][0] = base[0];
                bf[ni][1] = base[4*136];
            }
            #pragma unroll
            for (int mi = 0; mi < 4; mi++)
                #pragma unroll
                for (int ni = 0; ni < 4; ni++)
                    asm volatile(
                        "mma.sync.aligned.m16n8k8.row.col.f32.tf32.tf32.f32 "
                        "{%0,%1,%2,%3}, {%4,%5,%6,%7}, {%8,%9}, {%0,%1,%2,%3};"
                        : "+f"(acc[mi][ni][0]), "+f"(acc[mi][ni][1]),
                          "+f"(acc[mi][ni][2]), "+f"(acc[mi][ni][3])
                        : "r"(af[mi][0]), "r"(af[mi][1]), "r"(af[mi][2]), "r"(af[mi][3]),
                          "r"(bf[ni][0]), "r"(bf[ni][1]));
        }
        __syncthreads();
    }

    const bool lead = (z == 0);
    #pragma unroll
    for (int mi = 0; mi < 4; mi++) {
        int r0 = row0 + wm0 + mi*16 + g;
        #pragma unroll
        for (int ni = 0; ni < 4; ni++) {
            int c = col0 + wn0 + ni*8 + tc*2;
            if (c < N) {
                float v0 = acc[mi][ni][0], v1 = acc[mi][ni][1];
                float v2 = acc[mi][ni][2], v3 = acc[mi][ni][3];
                if (lead) {
                    float b0 = bias[c], b1 = bias[c+1];
                    v0 += b0; v1 += b1; v2 += b0; v3 += b1;
                    if (RES) {
                        v0 += Rr[(size_t)r0*N + c];     v1 += Rr[(size_t)r0*N + c + 1];
                        v2 += Rr[(size_t)(r0+8)*N + c]; v3 += Rr[(size_t)(r0+8)*N + c + 1];
                    }
                }
                atomicAdd(C + (size_t)r0*N + c,       v0);
                atomicAdd(C + (size_t)r0*N + c + 1,   v1);
                atomicAdd(C + (size_t)(r0+8)*N + c,   v2);
                atomicAdd(C + (size_t)(r0+8)*N + c+1, v3);
            }
        }
    }
}

// fused q/k/v projection
__global__ void __launch_bounds__(256, 2) gemm_qkv(
    const float* __restrict__ gqk, const float* __restrict__ gx,
    const float* __restrict__ wq, const float* __restrict__ bq, float* __restrict__ oq,
    const float* __restrict__ wk, const float* __restrict__ bk, float* __restrict__ ok,
    const float* __restrict__ wv, const float* __restrict__ bv, float* __restrict__ ov)
{
    const int z = blockIdx.z;
    if (z == 2) {
        gemm_body<0,0,1,1>(gx, wv, bv, nullptr, ov, 768, 768);
    } else if (z == 1) {
        gemm_body<0,0,0,1>(gqk, wk, bk, nullptr, ok, 768, 768);
    } else {
        gemm_body<0,0,0,1>(gqk, wq, bq, nullptr, oq, 768, 768);
    }
}

// ---------------- fused double conv for F=7 stage (order=2), exact fp32.
// Block: 64 t-rows x 64 d-cols. h window loaded once; conv1 results staged in smem.
// Zero-padding of h rows with t<0 reproduces the causal clamp exactly (gelu(0)=0,
// and fmaf(kv, 0, acc) == acc for finite kv).
#define C7_SMEM ((76*68 + 70*16 + 70*68)*4)
__global__ void __launch_bounds__(256) conv7_fused(
    const float* __restrict__ h, const float* __restrict__ p,
    float* __restrict__ out)
{
    extern __shared__ float csm[];
    float* hs = csm;                 // 76 x 68  (rows: t0-12 .. t0+63)
    float* ps = csm + 76*68;         // 70 x 16  (rows: t0-6 .. t0+63, 14 taps used)
    float* h1 = csm + 76*68 + 70*16; // 70 x 68  (rows: t0-6 .. t0+63)
    const int tid = threadIdx.x;
    const int d0  = blockIdx.x * 64;
    const int bt0 = blockIdx.y * 64;
    const int batch = bt0 / Lq;
    const int t0    = bt0 & (Lq - 1);

    // load h window (zero for t<0)
    for (int idx = tid; idx < 76*16; idx += 256) {
        int row = idx >> 4, c4 = (idx & 15) * 4;
        int lt = t0 - 12 + row;
        float4 v = make_float4(0.f, 0.f, 0.f, 0.f);
        if (lt >= 0)
            v = *(const float4*)(h + (size_t)(batch*Lq + lt) * Dq + d0 + c4);
        *(float4*)&hs[row*68 + c4] = v;
    }
    // load p rows (clamp OOB row index; values only ever multiply zeros)
    for (int idx = tid; idx < 70*14; idx += 256) {
        int row = idx / 14, c = idx % 14;
        int lt = t0 - 6 + row;
        int gbt = batch*Lq + (lt >= 0 ? lt : 0);
        ps[row*16 + c] = p[(size_t)gbt * 14 + c];
    }
    __syncthreads();

    // conv1 + gelu -> h1 rows 0..69 (t = t0-6+row), taps ps[row][0..6]
    for (int idx = tid; idx < 70*16; idx += 256) {
        int row = idx >> 4, c4 = (idx & 15) * 4;
        float ax = 0.f, ay = 0.f, az = 0.f, aw = 0.f;
        #pragma unroll
        for (int m = 6; m >= 0; --m) {
            float kv = ps[row*16 + m];
            const float4 hv = *(const float4*)&hs[(row + 6 - m)*68 + c4];
            ax = fmaf(kv, hv.x, ax);
            ay = fmaf(kv, hv.y, ay);
            az = fmaf(kv, hv.z, az);
            aw = fmaf(kv, hv.w, aw);
        }
        float4 o;
        o.x = gelu_f(ax); o.y = gelu_f(ay); o.z = gelu_f(az); o.w = gelu_f(aw);
        *(float4*)&h1[row*68 + c4] = o;
    }
    __syncthreads();

    // conv2 + gelu -> out rows 0..63 (t = t0+row), taps ps[row+6][7..13]
    for (int idx = tid; idx < 64*16; idx += 256) {
        int row = idx >> 4, c4 = (idx & 15) * 4;
        float ax = 0.f, ay = 0.f, az = 0.f, aw = 0.f;
        #pragma unroll
        for (int m = 6; m >= 0; --m) {
            float kv = ps[(row + 6)*16 + 7 + m];
            const float4 hv = *(const float4*)&h1[(row + 6 - m)*68 + c4];
            ax = fmaf(kv, hv.x, ax);
            ay = fmaf(kv, hv.y, ay);
            az = fmaf(kv, hv.z, az);
            aw = fmaf(kv, hv.w, aw);
        }
        float4 o;
        o.x = gelu_f(ax); o.y = gelu_f(ay); o.z = gelu_f(az); o.w = gelu_f(aw);
        *(float4*)(out + (size_t)(bt0 + row) * Dq + d0 + c4) = o;
    }
}

// ---------------- smem-tiled conv + GELU, register sliding window (R9 version)
#define CONV_SMEM ((128*68 + 64*68)*4)
template<int F>
__global__ void __launch_bounds__(256) conv_tiled(
    const float* __restrict__ h, const float* __restrict__ p,
    float* __restrict__ out, int pstride, int poff)
{
    extern __shared__ float csm[];
    float* hs = csm;            // 128 x 68
    float* ps = csm + 128*68;   // 64 x 68
    const int tid = threadIdx.x;
    const int d0  = blockIdx.x * 64;
    const int bt0 = blockIdx.y * 64;
    const int batch = bt0 / Lq;
    const int t0    = bt0 & (Lq - 1);
    const int tg = tid >> 4;
    const int dg = tid & 15;

    float4 acc[4];
    #pragma unroll
    for (int i = 0; i < 4; i++) acc[i] = make_float4(0.f, 0.f, 0.f, 0.f);

    for (int m0 = F - 64; m0 >= 0; m0 -= 64) {
        if (m0 != F - 64) __syncthreads();
        for (int idx = tid; idx < 128*16; idx += 256) {
            int row = idx >> 4, c4 = (idx & 15) * 4;
            int lt = t0 - m0 - 64 + row;
            float4 v = make_float4(0.f, 0.f, 0.f, 0.f);
            if (lt >= 0)
                v = *(const float4*)(h + (size_t)(batch*Lq + lt) * Dq + d0 + c4);
            *(float4*)&hs[row*68 + c4] = v;
        }
        for (int idx = tid; idx < 64*16; idx += 256) {
            int row = idx >> 4, c4 = (idx & 15) * 4;
            float4 v = *(const float4*)(p + (size_t)(bt0 + row) * pstride + poff + m0 + c4);
            *(float4*)&ps[row*68 + c4] = v;
        }
        __syncthreads();

        float4 win[4];
        #pragma unroll
        for (int j = 0; j < 4; j++)
            win[j] = *(const float4*)&hs[(tg*4 + 1 + j)*68 + dg*4];

        #pragma unroll
        for (int grp = 15; grp >= 0; --grp) {
            float pka[4][4];
            #pragma unroll
            for (int i = 0; i < 4; i++)
                *(float4*)pka[i] = *(const float4*)&ps[(tg*4 + i)*68 + grp*4];
            #pragma unroll
            for (int u = 3; u >= 0; --u) {
                const int mi = grp*4 + u;
                #pragma unroll
                for (int i = 0; i < 4; i++) {
                    float pk = pka[i][u];
                    acc[i].x = fmaf(pk, win[i].x, acc[i].x);
                    acc[i].y = fmaf(pk, win[i].y, acc[i].y);
                    acc[i].z = fmaf(pk, win[i].z, acc[i].z);
                    acc[i].w = fmaf(pk, win[i].w, acc[i].w);
                }
                if (mi > 0) {
                    win[0] = win[1]; win[1] = win[2]; win[2] = win[3];
                    win[3] = *(const float4*)&hs[(tg*4 + 68 - mi)*68 + dg*4];
                }
            }
        }
    }

    #pragma unroll
    for (int i = 0; i < 4; i++) {
        float4 o;
        o.x = gelu_f(acc[i].x); o.y = gelu_f(acc[i].y);
        o.z = gelu_f(acc[i].z); o.w = gelu_f(acc[i].w);
        *(float4*)(out + (size_t)(bt0 + tg*4 + i) * Dq + d0 + dg*4) = o;
    }
}

// ---------------- LayerNorm of (a+b): two-pass, fp64 accumulators
__global__ void ln_kernel(const float* __restrict__ a, const float* __restrict__ b,
                          const float* __restrict__ g, const float* __restrict__ be,
                          float* __restrict__ out)
{
    __shared__ double red[10];
    int row = blockIdx.x, tid = threadIdx.x;
    const float* pa = a + (size_t)row * Dq;
    const float* pb = b + (size_t)row * Dq;
    float v[3];
    double s = 0.0;
    #pragma unroll
    for (int i = 0; i < 3; i++) {
        float x = pa[tid + 256*i] + pb[tid + 256*i];
        v[i] = x; s += (double)x;
    }
    #pragma unroll
    for (int o = 16; o; o >>= 1) s += __shfl_down_sync(0xffffffffu, s, o);
    if ((tid & 31) == 0) red[tid >> 5] = s;
    __syncthreads();
    if (tid == 0) {
        double t = 0.0;
        #pragma unroll
        for (int w = 0; w < 8; w++) t += red[w];
        red[8] = t * (1.0/768.0);
    }
    __syncthreads();
    float mean = (float)red[8];

    double s2 = 0.0;
    #pragma unroll
    for (int i = 0; i < 3; i++) {
        double d = (double)v[i] - red[8];
        s2 += d * d;
    }
    #pragma unroll
    for (int o = 16; o; o >>= 1) s2 += __shfl_down_sync(0xffffffffu, s2, o);
    if ((tid & 31) == 0) red[tid >> 5] = s2;
    __syncthreads();
    if (tid == 0) {
        double t = 0.0;
        #pragma unroll
        for (int w = 0; w < 8; w++) t += red[w];
        red[9] = 1.0 / sqrt(t * (1.0/768.0) + 1e-5);
    }
    __syncthreads();
    float rs = (float)red[9];
    #pragma unroll
    for (int i = 0; i < 3; i++) {
        int c = tid + 256*i;
        out[(size_t)row * Dq + c] = (v[i] - mean) * rs * g[c] + be[c];
    }
}

// ---------------- fused LayerNorm(a+b) + RoPE
__global__ void ln_rope_kernel(const float* __restrict__ a, const float* __restrict__ b,
                               const float* __restrict__ g, const float* __restrict__ be,
                               const float* __restrict__ sn, const float* __restrict__ cs,
                               float* __restrict__ ox, float* __restrict__ oqk)
{
    __shared__ double red[10];
    __shared__ float srow[768];
    int row = blockIdx.x, tid = threadIdx.x;
    int l = row & (Lq - 1);
    const float* pa = a + (size_t)row * Dq;
    const float* pb = b + (size_t)row * Dq;
    float v[3];
    double s = 0.0;
    #pragma unroll
    for (int i = 0; i < 3; i++) {
        float x = pa[tid + 256*i] + pb[tid + 256*i];
        v[i] = x; s += (double)x;
    }
    #pragma unroll
    for (int o = 16; o; o >>= 1) s += __shfl_down_sync(0xffffffffu, s, o);
    if ((tid & 31) == 0) red[tid >> 5] = s;
    __syncthreads();
    if (tid == 0) {
        double t = 0.0;
        #pragma unroll
        for (int w = 0; w < 8; w++) t += red[w];
        red[8] = t * (1.0/768.0);
    }
    __syncthreads();
    float mean = (float)red[8];

    double s2 = 0.0;
    #pragma unroll
    for (int i = 0; i < 3; i++) {
        double d = (double)v[i] - red[8];
        s2 += d * d;
    }
    #pragma unroll
    for (int o = 16; o; o >>= 1) s2 += __shfl_down_sync(0xffffffffu, s2, o);
    if ((tid & 31) == 0) red[tid >> 5] = s2;
    __syncthreads();
    if (tid == 0) {
        double t = 0.0;
        #pragma unroll
        for (int w = 0; w < 8; w++) t += red[w];
        red[9] = 1.0 / sqrt(t * (1.0/768.0) + 1e-5);
    }
    __syncthreads();
    float rs = (float)red[9];
    #pragma unroll
    for (int i = 0; i < 3; i++) {
        int c = tid + 256*i;
        float y = (v[i] - mean) * rs * g[c] + be[c];
        ox[(size_t)row * Dq + c] = y;
        srow[c] = y;
    }
    __syncthreads();
    #pragma unroll
    for (int i = 0; i < 3; i++) {
        int c = tid + 256*i;
        float r;
        if (c < 384) {
            float sv = sn[l*384 + c], cv = cs[l*384 + c];
            r = srow[c] * cv - srow[c + 384] * sv;
        } else {
            int d = c - 384;
            float sv = sn[l*384 + d], cv = cs[l*384 + d];
            r = srow[c] * cv + srow[d] * sv;
        }
        oqk[(size_t)row * Dq + c] = tf32r(r);
    }
}

// ---------------- tensor-core flash attention, hd=64; R13 config
#define ATS 68
#define VTS 72
#define PS  68
#define ATT_SMEM ((64*ATS + 64*VTS + 64*PS)*4)
__global__ void __launch_bounds__(128, 3) attn_mma(
    const float* __restrict__ Q, const float* __restrict__ K,
    const float* __restrict__ V, float* __restrict__ O)
{
    extern __shared__ float sm[];
    float* Ks = sm;
    float* Vs = sm + 64*ATS;
    float* Ps = sm + 64*ATS + 64*VTS;
    const int tid = threadIdx.x;
    const int warp = tid >> 5, lane = tid & 31;
    const int g = lane >> 2, tc = lane & 3;
    const int bh = blockIdx.y;
    const int b = bh / Hq, h = bh % Hq;
    const int q0 = blockIdx.x * 64;
    const size_t base = (size_t)b * Lq * Dq + (size_t)h * 64;
    const int rlo = warp*16 + g;

    uint32_t qa[8][4];
    {
        const float* qr0 = Q + base + (size_t)(q0 + rlo) * Dq;
        const float* qr1 = Q + base + (size_t)(q0 + rlo + 8) * Dq;
        #pragma unroll
        for (int i = 0; i < 8; i++) {
            int k8 = i * 8;
            qa[i][0] = __float_as_uint(qr0[k8 + tc]);
            qa[i][1] = __float_as_uint(qr1[k8 + tc]);
            qa[i][2] = __float_as_uint(qr0[k8 + tc + 4]);
            qa[i][3] = __float_as_uint(qr1[k8 + tc + 4]);
        }
    }

    float m0r = -INFINITY, m1r = -INFINITY, l0 = 0.f, l1 = 0.f;
    float o[8][4];
    #pragma unroll
    for (int ni = 0; ni < 8; ni++)
        #pragma unroll
        for (int j = 0; j < 4; j++) o[ni][j] = 0.f;

    for (int kt = 0; kt < Lq/64; ++kt) {
        __syncthreads();
        for (int i = tid; i < 64*16; i += 128) {
            int rr = i >> 4, c4 = (i & 15) * 4;
            *(float4*)&Ks[rr*ATS + c4] = *(const float4*)(K + base + (size_t)(kt*64 + rr) * Dq + c4);
            *(float4*)&Vs[rr*VTS + c4] = *(const float4*)(V + base + (size_t)(kt*64 + rr) * Dq + c4);
        }
        __syncthreads();

        float s[8][4];
        #pragma unroll
        for (int ni = 0; ni < 8; ni++)
            #pragma unroll
            for (int j = 0; j < 4; j++) s[ni][j] = 0.f;
        #pragma unroll
        for (int i8 = 0; i8 < 8; i8++) {
            const int k8 = i8 * 8;
            #pragma unroll
            for (int ni = 0; ni < 8; ni++) {
                uint32_t b0 = __float_as_uint(Ks[(ni*8 + g)*ATS + k8 + tc]);
                uint32_t b1 = __float_as_uint(Ks[(ni*8 + g)*ATS + k8 + tc + 4]);
                asm volatile(
                    "mma.sync.aligned.m16n8k8.row.col.f32.tf32.tf32.f32 "
                    "{%0,%1,%2,%3}, {%4,%5,%6,%7}, {%8,%9}, {%0,%1,%2,%3};"
                    : "+f"(s[ni][0]), "+f"(s[ni][1]), "+f"(s[ni][2]), "+f"(s[ni][3])
                    : "r"(qa[i8][0]), "r"(qa[i8][1]), "r"(qa[i8][2]), "r"(qa[i8][3]),
                      "r"(b0), "r"(b1));
            }
        }
        #pragma unroll
        for (int ni = 0; ni < 8; ni++)
            #pragma unroll
            for (int j = 0; j < 4; j++) s[ni][j] *= 0.125f;

        float mx0 = -INFINITY, mx1 = -INFINITY;
        #pragma unroll
        for (int ni = 0; ni < 8; ni++) {
            mx0 = fmaxf(mx0, fmaxf(s[ni][0], s[ni][1]));
            mx1 = fmaxf(mx1, fmaxf(s[ni][2], s[ni][3]));
        }
        mx0 = fmaxf(mx0, __shfl_xor_sync(0xffffffffu, mx0, 1));
        mx0 = fmaxf(mx0, __shfl_xor_sync(0xffffffffu, mx0, 2));
        mx1 = fmaxf(mx1, __shfl_xor_sync(0xffffffffu, mx1, 1));
        mx1 = fmaxf(mx1, __shfl_xor_sync(0xffffffffu, mx1, 2));
        float mn0 = fmaxf(m0r, mx0), mn1 = fmaxf(m1r, mx1);
        float ps0 = 0.f, ps1 = 0.f;
        #pragma unroll
        for (int ni = 0; ni < 8; ni++) {
            s[ni][0] = __expf(s[ni][0] - mn0); ps0 += s[ni][0];
            s[ni][1] = __expf(s[ni][1] - mn0); ps0 += s[ni][1];
            s[ni][2] = __expf(s[ni][2] - mn1); ps1 += s[ni][2];
            s[ni][3] = __expf(s[ni][3] - mn1); ps1 += s[ni][3];
        }
        ps0 += __shfl_xor_sync(0xffffffffu, ps0, 1);
        ps0 += __shfl_xor_sync(0xffffffffu, ps0, 2);
        ps1 += __shfl_xor_sync(0xffffffffu, ps1, 1);
        ps1 += __shfl_xor_sync(0xffffffffu, ps1, 2);
        float al0 = __expf(m0r - mn0), al1 = __expf(m1r - mn1);
        l0 = l0 * al0 + ps0;  m0r = mn0;
        l1 = l1 * al1 + ps1;  m1r = mn1;
        #pragma unroll
        for (int ni = 0; ni < 8; ni++) {
            o[ni][0] *= al0; o[ni][1] *= al0;
            o[ni][2] *= al1; o[ni][3] *= al1;
        }

        #pragma unroll
        for (int ni = 0; ni < 8; ni++) {
            *(float2*)&Ps[rlo*PS + ni*8 + 2*tc] =
                make_float2(tf32r(s[ni][0]), tf32r(s[ni][1]));
            *(float2*)&Ps[(rlo+8)*PS + ni*8 + 2*tc] =
                make_float2(tf32r(s[ni][2]), tf32r(s[ni][3]));
        }
        __syncwarp();

        #pragma unroll
        for (int k8 = 0; k8 < 64; k8 += 8) {
            uint32_t a0 = __float_as_uint(Ps[(warp*16 + g)*PS + k8 + tc]);
            uint32_t a1 = __float_as_uint(Ps[(warp*16 + g + 8)*PS + k8 + tc]);
            uint32_t a2 = __float_as_uint(Ps[(warp*16 + g)*PS + k8 + tc + 4]);
            uint32_t a3 = __float_as_uint(Ps[(warp*16 + g + 8)*PS + k8 + tc + 4]);
            #pragma unroll
            for (int ni = 0; ni < 8; ni++) {
                uint32_t b0 = __float_as_uint(Vs[(k8 + tc)*VTS + ni*8 + g]);
                uint32_t b1 = __float_as_uint(Vs[(k8 + tc + 4)*VTS + ni*8 + g]);
                asm volatile(
                    "mma.sync.aligned.m16n8k8.row.col.f32.tf32.tf32.f32 "
                    "{%0,%1,%2,%3}, {%4,%5,%6,%7}, {%8,%9}, {%0,%1,%2,%3};"
                    : "+f"(o[ni][0]), "+f"(o[ni][1]), "+f"(o[ni][2]), "+f"(o[ni][3])
                    : "r"(a0), "r"(a1), "r"(a2), "r"(a3), "r"(b0), "r"(b1));
            }
        }
    }

    float inv0 = 1.f / l0, inv1 = 1.f / l1;
    #pragma unroll
    for (int ni = 0; ni < 8; ni++) {
        *(float2*)(O + base + (size_t)(q0 + rlo) * Dq + ni*8 + 2*tc) =
            make_float2(tf32r(o[ni][0]*inv0), tf32r(o[ni][1]*inv0));
        *(float2*)(O + base + (size_t)(q0 + rlo + 8) * Dq + ni*8 + 2*tc) =
            make_float2(tf32r(o[ni][2]*inv1), tf32r(o[ni][3]*inv1));
    }
}

// ---------------- host orchestration ----------------
extern "C" void kernel_launch(void* const* d_in, const int* in_sizes, int n_in,
                              void* d_out, int out_size)
{
    (void)n_in; (void)out_size;
    const float* x   = (const float*)d_in[0];
    const float* sn  = (const float*)d_in[1];
    const float* cs  = (const float*)d_in[2];
    const float* w1s[3] = {(const float*)d_in[3], (const float*)d_in[7],  (const float*)d_in[11]};
    const float* b1s[3] = {(const float*)d_in[4], (const float*)d_in[8],  (const float*)d_in[12]};
    const float* w2s[3] = {(const float*)d_in[5], (const float*)d_in[9],  (const float*)d_in[13]};
    const float* b2s[3] = {(const float*)d_in[6], (const float*)d_in[10], (const float*)d_in[14]};
    const float* ln1g = (const float*)d_in[15];
    const float* ln1b = (const float*)d_in[16];
    const float* ln2g = (const float*)d_in[17];
    const float* ln2b = (const float*)d_in[18];

    const float *wq, *bqv, *wk, *bkv, *wv, *bvv, *wo, *bov;
    if (in_sizes[20] == 768) {
        wq = (const float*)d_in[19]; bqv = (const float*)d_in[20];
        wk = (const float*)d_in[21]; bkv = (const float*)d_in[22];
        wv = (const float*)d_in[23]; bvv = (const float*)d_in[24];
        wo = (const float*)d_in[25]; bov = (const float*)d_in[26];
    } else {
        wq = (const float*)d_in[19]; wk  = (const float*)d_in[20];
        wv = (const float*)d_in[21]; wo  = (const float*)d_in[22];
        bqv = (const float*)d_in[23]; bkv = (const float*)d_in[24];
        bvv = (const float*)d_in[25]; bov = (const float*)d_in[26];
    }
    const float* mw1 = (const float*)d_in[27]; const float* mb1 = (const float*)d_in[28];
    const float* mw2 = (const float*)d_in[29]; const float* mb2 = (const float*)d_in[30];

    float *t1, *pp, *ha, *hb, *gx, *gqk, *gq, *gk, *gv, *gatt, *go, *gx2, *wr;
    cudaGetSymbolAddress((void**)&t1,  g_t1);
    cudaGetSymbolAddress((void**)&pp,  g_p);
    cudaGetSymbolAddress((void**)&ha,  g_ha);
    cudaGetSymbolAddress((void**)&hb,  g_hb);
    cudaGetSymbolAddress((void**)&gx,  g_x);
    cudaGetSymbolAddress((void**)&gqk, g_qk);
    cudaGetSymbolAddress((void**)&gq,  g_q);
    cudaGetSymbolAddress((void**)&gk,  g_k);
    cudaGetSymbolAddress((void**)&gv,  g_v);
    cudaGetSymbolAddress((void**)&gatt,g_att);
    cudaGetSymbolAddress((void**)&go,  g_o);
    cudaGetSymbolAddress((void**)&gx2, g_x2);
    cudaGetSymbolAddress((void**)&wr,  g_wr);

    WSrc ws;
    ws.s[0] = (const float4*)w1s[0]; ws.s[1] = (const float4*)w1s[1];
    ws.s[2] = (const float4*)w1s[2]; ws.s[3] = (const float4*)w2s[0];
    ws.s[4] = (const float4*)w2s[1]; ws.s[5] = (const float4*)w2s[2];
    ws.s[6] = (const float4*)wq;     ws.s[7] = (const float4*)wk;
    ws.s[8] = (const float4*)wv;     ws.s[9] = (const float4*)wo;
    ws.s[10] = (const float4*)mw1;   ws.s[11] = (const float4*)mw2;
    round_all<<<(W_TOTAL4 + 255)/256, 256>>>(ws, (float4*)wr);

    const float* rw1[3] = {wr, wr + 2359296, wr + 4718592};
    const float* rw2[3] = {wr + 7077888, wr + 7120896, wr + 8300544};
    const float *rwq = wr + 11446272, *rwk = wr + 12036096;
    const float *rwv = wr + 12625920, *rwo = wr + 13215744;
    const float *rmw1 = wr + 13805568, *rmw2 = wr + 16164864;

    cudaFuncSetAttribute(gemm_tc<1,0,1,1>, cudaFuncAttributeMaxDynamicSharedMemorySize, GEMM_SMEM);
    cudaFuncSetAttribute(gemm_tc<0,0,0,0>, cudaFuncAttributeMaxDynamicSharedMemorySize, GEMM_SMEM);
    cudaFuncSetAttribute(gemm_tc_sk<0>,    cudaFuncAttributeMaxDynamicSharedMemorySize, GEMM_SMEM);
    cudaFuncSetAttribute(gemm_tc_sk<1>,    cudaFuncAttributeMaxDynamicSharedMemorySize, GEMM_SMEM);
    cudaFuncSetAttribute(gemm_qkv,         cudaFuncAttributeMaxDynamicSharedMemorySize, GEMM_SMEM);
    cudaFuncSetAttribute(conv7_fused,      cudaFuncAttributeMaxDynamicSharedMemorySize, C7_SMEM);
    cudaFuncSetAttribute(conv_tiled<128>,  cudaFuncAttributeMaxDynamicSharedMemorySize, CONV_SMEM);
    cudaFuncSetAttribute(conv_tiled<256>,  cudaFuncAttributeMaxDynamicSharedMemorySize, CONV_SMEM);
    cudaFuncSetAttribute(attn_mma,         cudaFuncAttributeMaxDynamicSharedMemorySize, ATT_SMEM);

    const int orderF[3] = {14, 384, 1024};
    const int Fs[3]     = {7, 128, 256};
    const int ords[3]   = {2, 3, 4};
    const int skS[3]    = {8, 4, 2};
    const int skKC[3]   = {384, 768, 1536};

    const float* hcur = x;
    float* bufs[2] = {ha, hb};
    int cur = 0;

    for (int s3 = 0; s3 < 3; s3++) {
        gemm_tc<1,0,1,1><<<dim3(24,32), 256, GEMM_SMEM>>>(hcur, rw1[s3], b1s[s3], nullptr, t1, 3072, 768);
        cudaMemsetAsync(pp, 0, sizeof(float)*(size_t)ROWS*orderF[s3]);
        gemm_tc_sk<0><<<dim3((orderF[s3]+127)/128, 32, skS[s3]), 256, GEMM_SMEM>>>(
            t1, rw2[s3], b2s[s3], nullptr, pp, orderF[s3], 3072, skKC[s3]);
        if (Fs[s3] == 7) {
            // fused double conv (order = 2)
            conv7_fused<<<dim3(12,64), 256, C7_SMEM>>>(hcur, pp, bufs[cur]);
            hcur = bufs[cur];
            cur ^= 1;
        } else {
            for (int i = 0; i < ords[s3]; i++) {
                if (Fs[s3] == 128)
                    conv_tiled<128><<<dim3(12,64), 256, CONV_SMEM>>>(hcur, pp, bufs[cur], orderF[s3], i * 128);
                else
                    conv_tiled<256><<<dim3(12,64), 256, CONV_SMEM>>>(hcur, pp, bufs[cur], orderF[s3], i * 256);
                hcur = bufs[cur];
                cur ^= 1;
            }
        }
    }

    ln_rope_kernel<<<ROWS, 256>>>(x, hcur, ln1g, ln1b, sn, cs, gx, gqk);

    gemm_qkv<<<dim3(6,32,3), 256, GEMM_SMEM>>>(gqk, gx, rwq, bqv, gq, rwk, bkv, gk, rwv, bvv, gv);

    attn_mma<<<dim3(Lq/64, Bq*Hq), 128, ATT_SMEM>>>(gq, gk, gv, gatt);

    cudaMemsetAsync(go, 0, sizeof(float)*(size_t)ROWS*768);
    gemm_tc_sk<0><<<dim3(6,32,2), 256, GEMM_SMEM>>>(
        gatt, rwo, bov, nullptr, go, 768, 768, 384);

    ln_kernel<<<ROWS, 256>>>(gx, go, ln2g, ln2b, gx2);
    gemm_tc<1,0,1,1><<<dim3(24,32), 256, GEMM_SMEM>>>(gx2, rmw1, mb1, nullptr, t1, 3072, 768);
    cudaMemsetAsync(d_out, 0, sizeof(float)*(size_t)ROWS*768);
    gemm_tc_sk<1><<<dim3(6,32,2), 256, GEMM_SMEM>>>(
        t1, rmw2, mb2, gx2, (float*)d_out, 768, 3072, 1536);
}

// round 17
// speedup vs baseline: 1.0016x; 1.0016x over previous
#include <cuda_runtime.h>
#include <math.h>
#include <stdint.h>

#define Bq 2
#define Lq 2048
#define Dq 768
#define Hq 12
#define ROWS (Bq*Lq)   /* 4096 */

// ---------------- scratch (device globals; no allocation allowed) ----------------
__device__ float g_t1[(size_t)ROWS*3072];
__device__ float g_p [(size_t)ROWS*1024];
__device__ float g_ha[(size_t)ROWS*Dq];
__device__ float g_hb[(size_t)ROWS*Dq];
__device__ float g_x [(size_t)ROWS*Dq];
__device__ float g_qk[(size_t)ROWS*Dq];
__device__ float g_q [(size_t)ROWS*Dq];
__device__ float g_k [(size_t)ROWS*Dq];
__device__ float g_v [(size_t)ROWS*Dq];
__device__ float g_att[(size_t)ROWS*Dq];
__device__ float g_o [(size_t)ROWS*Dq];
__device__ float g_x2[(size_t)ROWS*Dq];
__device__ float g_wr[18524160];   // pre-rounded weights (74MB), contiguous

__device__ __forceinline__ float gelu_f(float x){
    return 0.5f*x*(1.0f+erff(x*0.70710678118654752440f));
}
__device__ __forceinline__ uint32_t tf32u(float x){
    uint32_t u;
    asm("cvt.rna.tf32.f32 %0, %1;" : "=r"(u) : "f"(x));
    return u;
}
__device__ __forceinline__ float tf32r(float x){
    return __uint_as_float(tf32u(x));
}
__device__ __forceinline__ void cp16(uint32_t smem_dst, const void* gsrc){
    asm volatile("cp.async.ca.shared.global [%0], [%1], 16;\n"
                 :: "r"(smem_dst), "l"(gsrc));
}

// ---------------- merged tf32 round-copy of all 12 weight matrices ----------------
struct WSrc { const float4* s[12]; };
#define W_TOTAL4 4631040
__global__ void round_all(WSrc w, float4* __restrict__ dst)
{
    const int end4[12] = {589824, 1179648, 1769472, 1780224, 2075136, 2861568,
                          3009024, 3156480, 3303936, 3451392, 4041216, 4631040};
    int i = blockIdx.x * blockDim.x + threadIdx.x;
    if (i >= W_TOTAL4) return;
    int s = 0;
    #pragma unroll
    for (int k = 0; k < 12; k++) if (i >= end4[k]) s = k + 1;
    int st = (s == 0) ? 0 : end4[s-1];
    float4 v = w.s[s][i - st];
    dst[i] = make_float4(tf32r(v.x), tf32r(v.y), tf32r(v.z), tf32r(v.w));
}

// ---------------- tensor-core TF32 GEMM body, 2-stage cp.async pipeline
#define GEMM_SMEM (2*(128*36 + 32*136)*4)
template<int GELU, int RES, int CVTA, int ROUT>
__device__ __forceinline__ void gemm_body(
    const float* __restrict__ A, const float* __restrict__ Bm,
    const float* __restrict__ bias, const float* __restrict__ Rr,
    float* __restrict__ C, int N, int K)
{
    extern __shared__ uint32_t smem_u[];
    uint32_t* AsB = smem_u;
    uint32_t* BsB = smem_u + 2*128*36;
    const int tid  = threadIdx.x;
    const int warp = tid >> 5, lane = tid & 31;
    const int g = lane >> 2, tc = lane & 3;
    const int wm0 = (warp & 1) * 64, wn0 = (warp >> 1) * 32;
    const int row0 = blockIdx.y * 128, col0 = blockIdx.x * 128;
    const bool colFull = (col0 + 128 <= N);

    float acc[4][4][4] = {};
    const int ar = tid >> 3,  ac = (tid & 7) * 4;
    const int bk = tid >> 5,  bc = (tid & 31) * 4;
    const int nt = K / 32;

    auto issue = [&](int kt, int s){
        uint32_t* as = AsB + s * (128*36);
        uint32_t* bs = BsB + s * (32*136);
        const int k0 = kt * 32;
        #pragma unroll
        for (int p = 0; p < 4; p++) {
            int r = ar + p * 32;
            cp16((uint32_t)__cvta_generic_to_shared(&as[r*36 + ac]),
                 A + (size_t)(row0 + r) * K + k0 + ac);
        }
        if (colFull) {
            #pragma unroll
            for (int p = 0; p < 4; p++) {
                int kr = bk + p * 8;
                cp16((uint32_t)__cvta_generic_to_shared(&bs[kr*136 + bc]),
                     Bm + (size_t)(k0 + kr) * N + col0 + bc);
            }
        } else {
            #pragma unroll
            for (int p = 0; p < 4; p++) {
                int kr = bk + p * 8;
                #pragma unroll
                for (int u = 0; u < 4; u++) {
                    int c = col0 + bc + u;
                    bs[kr*136 + bc + u] =
                        (c < N) ? __float_as_uint(Bm[(size_t)(k0 + kr) * N + c]) : 0u;
                }
            }
        }
        asm volatile("cp.async.commit_group;\n");
    };

    issue(0, 0);
    for (int kt = 0; kt < nt; kt++) {
        const int cur = kt & 1;
        if (kt + 1 < nt) {
            issue(kt + 1, cur ^ 1);
            asm volatile("cp.async.wait_group 1;\n");
        } else {
            asm volatile("cp.async.wait_group 0;\n");
        }
        __syncthreads();
        const uint32_t* as = AsB + cur * (128*36);
        const uint32_t* bs = BsB + cur * (32*136);
        #pragma unroll
        for (int k8 = 0; k8 < 32; k8 += 8) {
            uint32_t af[4][4], bf[4][2];
            #pragma unroll
            for (int mi = 0; mi < 4; mi++) {
                const uint32_t* base = &as[(wm0 + mi*16 + g) * 36 + k8 + tc];
                if (CVTA) {
                    af[mi][0] = tf32u(__uint_as_float(base[0]));
                    af[mi][1] = tf32u(__uint_as_float(base[8*36]));
                    af[mi][2] = tf32u(__uint_as_float(base[4]));
                    af[mi][3] = tf32u(__uint_as_float(base[8*36 + 4]));
                } else {
                    af[mi][0] = base[0];
                    af[mi][1] = base[8*36];
                    af[mi][2] = base[4];
                    af[mi][3] = base[8*36 + 4];
                }
            }
            #pragma unroll
            for (int ni = 0; ni < 4; ni++) {
                const uint32_t* base = &bs[(k8 + tc) * 136 + wn0 + ni*8 + g];
                bf[ni][0] = base[0];
                bf[ni][1] = base[4*136];
            }
            #pragma unroll
            for (int mi = 0; mi < 4; mi++)
                #pragma unroll
                for (int ni = 0; ni < 4; ni++)
                    asm volatile(
                        "mma.sync.aligned.m16n8k8.row.col.f32.tf32.tf32.f32 "
                        "{%0,%1,%2,%3}, {%4,%5,%6,%7}, {%8,%9}, {%0,%1,%2,%3};"
                        : "+f"(acc[mi][ni][0]), "+f"(acc[mi][ni][1]),
                          "+f"(acc[mi][ni][2]), "+f"(acc[mi][ni][3])
                        : "r"(af[mi][0]), "r"(af[mi][1]), "r"(af[mi][2]), "r"(af[mi][3]),
                          "r"(bf[ni][0]), "r"(bf[ni][1]));
        }
        __syncthreads();
    }

    #pragma unroll
    for (int mi = 0; mi < 4; mi++) {
        int r0 = row0 + wm0 + mi*16 + g;
        #pragma unroll
        for (int ni = 0; ni < 4; ni++) {
            int c = col0 + wn0 + ni*8 + tc*2;
            if (c < N) {
                float b0 = bias[c], b1 = bias[c+1];
                float v0 = acc[mi][ni][0] + b0, v1 = acc[mi][ni][1] + b1;
                float v2 = acc[mi][ni][2] + b0, v3 = acc[mi][ni][3] + b1;
                if (GELU) { v0 = gelu_f(v0); v1 = gelu_f(v1); v2 = gelu_f(v2); v3 = gelu_f(v3); }
                if (ROUT) { v0 = tf32r(v0); v1 = tf32r(v1); v2 = tf32r(v2); v3 = tf32r(v3); }
                if (RES) {
                    v0 += Rr[(size_t)r0*N + c];     v1 += Rr[(size_t)r0*N + c + 1];
                    v2 += Rr[(size_t)(r0+8)*N + c]; v3 += Rr[(size_t)(r0+8)*N + c + 1];
                }
                *(float2*)(C + (size_t)r0*N + c)     = make_float2(v0, v1);
                *(float2*)(C + (size_t)(r0+8)*N + c) = make_float2(v2, v3);
            }
        }
    }
}

template<int GELU, int RES, int CVTA, int ROUT>
__global__ void __launch_bounds__(256, 2) gemm_tc(
    const float* __restrict__ A, const float* __restrict__ Bm,
    const float* __restrict__ bias, const float* __restrict__ Rr,
    float* __restrict__ C, int N, int K)
{
    gemm_body<GELU, RES, CVTA, ROUT>(A, Bm, bias, Rr, C, N, K);
}

// ---------------- split-K TF32 GEMM: C += chunk via atomicAdd (C pre-zeroed)
template<int RES>
__global__ void __launch_bounds__(256, 2) gemm_tc_sk(
    const float* __restrict__ A, const float* __restrict__ Bm,
    const float* __restrict__ bias, const float* __restrict__ Rr,
    float* __restrict__ C, int N, int K, int KC)
{
    extern __shared__ uint32_t smem_u[];
    uint32_t* AsB = smem_u;
    uint32_t* BsB = smem_u + 2*128*36;
    const int tid  = threadIdx.x;
    const int warp = tid >> 5, lane = tid & 31;
    const int g = lane >> 2, tc = lane & 3;
    const int wm0 = (warp & 1) * 64, wn0 = (warp >> 1) * 32;
    const int row0 = blockIdx.y * 128, col0 = blockIdx.x * 128;
    const int z = blockIdx.z;
    const int kbase = z * KC;
    const bool colFull = (col0 + 128 <= N);

    float acc[4][4][4] = {};
    const int ar = tid >> 3,  ac = (tid & 7) * 4;
    const int bk = tid >> 5,  bc = (tid & 31) * 4;
    const int nt = KC / 32;

    auto issue = [&](int kt, int s){
        uint32_t* as = AsB + s * (128*36);
        uint32_t* bs = BsB + s * (32*136);
        const int k0 = kbase + kt * 32;
        #pragma unroll
        for (int p = 0; p < 4; p++) {
            int r = ar + p * 32;
            cp16((uint32_t)__cvta_generic_to_shared(&as[r*36 + ac]),
                 A + (size_t)(row0 + r) * K + k0 + ac);
        }
        if (colFull) {
            #pragma unroll
            for (int p = 0; p < 4; p++) {
                int kr = bk + p * 8;
                cp16((uint32_t)__cvta_generic_to_shared(&bs[kr*136 + bc]),
                     Bm + (size_t)(k0 + kr) * N + col0 + bc);
            }
        } else {
            #pragma unroll
            for (int p = 0; p < 4; p++) {
                int kr = bk + p * 8;
                #pragma unroll
                for (int u = 0; u < 4; u++) {
                    int c = col0 + bc + u;
                    bs[kr*136 + bc + u] =
                        (c < N) ? __float_as_uint(Bm[(size_t)(k0 + kr) * N + c]) : 0u;
                }
            }
        }
        asm volatile("cp.async.commit_group;\n");
    };

    issue(0, 0);
    for (int kt = 0; kt < nt; kt++) {
        const int cur = kt & 1;
        if (kt + 1 < nt) {
            issue(kt + 1, cur ^ 1);
            asm volatile("cp.async.wait_group 1;\n");
        } else {
            asm volatile("cp.async.wait_group 0;\n");
        }
        __syncthreads();
        const uint32_t* as = AsB + cur * (128*36);
        const uint32_t* bs = BsB + cur * (32*136);
        #pragma unroll
        for (int k8 = 0; k8 < 32; k8 += 8) {
            uint32_t af[4][4], bf[4][2];
            #pragma unroll
            for (int mi = 0; mi < 4; mi++) {
                const uint32_t* base = &as[(wm0 + mi*16 + g) * 36 + k8 + tc];
                af[mi][0] = base[0];
                af[mi][1] = base[8*36];
                af[mi][2] = base[4];
                af[mi][3] = base[8*36 + 4];
            }
            #pragma unroll
            for (int ni = 0; ni < 4; ni++) {
                const uint32_t* base = &bs[(k8 + tc) * 136 + wn0 + ni*8 + g];
                bf[ni][0] = base[0];
                bf[ni][1] = base[4*136];
            }
            #pragma unroll
            for (int mi = 0; mi < 4; mi++)
                #pragma unroll
                for (int ni = 0; ni < 4; ni++)
                    asm volatile(
                        "mma.sync.aligned.m16n8k8.row.col.f32.tf32.tf32.f32 "
                        "{%0,%1,%2,%3}, {%4,%5,%6,%7}, {%8,%9}, {%0,%1,%2,%3};"
                        : "+f"(acc[mi][ni][0]), "+f"(acc[mi][ni][1]),
                          "+f"(acc[mi][ni][2]), "+f"(acc[mi][ni][3])
                        : "r"(af[mi][0]), "r"(af[mi][1]), "r"(af[mi][2]), "r"(af[mi][3]),
                          "r"(bf[ni][0]), "r"(bf[ni][1]));
        }
        __syncthreads();
    }

    const bool lead = (z == 0);
    #pragma unroll
    for (int mi = 0; mi < 4; mi++) {
        int r0 = row0 + wm0 + mi*16 + g;
        #pragma unroll
        for (int ni = 0; ni < 4; ni++) {
            int c = col0 + wn0 + ni*8 + tc*2;
            if (c < N) {
                float v0 = acc[mi][ni][0], v1 = acc[mi][ni][1];
                float v2 = acc[mi][ni][2], v3 = acc[mi][ni][3];
                if (lead) {
                    float b0 = bias[c], b1 = bias[c+1];
                    v0 += b0; v1 += b1; v2 += b0; v3 += b1;
                    if (RES) {
                        v0 += Rr[(size_t)r0*N + c];     v1 += Rr[(size_t)r0*N + c + 1];
                        v2 += Rr[(size_t)(r0+8)*N + c]; v3 += Rr[(size_t)(r0+8)*N + c + 1];
                    }
                }
                atomicAdd(C + (size_t)r0*N + c,       v0);
                atomicAdd(C + (size_t)r0*N + c + 1,   v1);
                atomicAdd(C + (size_t)(r0+8)*N + c,   v2);
                atomicAdd(C + (size_t)(r0+8)*N + c+1, v3);
            }
        }
    }
}

// fused q/k/v projection
__global__ void __launch_bounds__(256, 2) gemm_qkv(
    const float* __restrict__ gqk, const float* __restrict__ gx,
    const float* __restrict__ wq, const float* __restrict__ bq, float* __restrict__ oq,
    const float* __restrict__ wk, const float* __restrict__ bk, float* __restrict__ ok,
    const float* __restrict__ wv, const float* __restrict__ bv, float* __restrict__ ov)
{
    const int z = blockIdx.z;
    if (z == 2) {
        gemm_body<0,0,1,1>(gx, wv, bv, nullptr, ov, 768, 768);
    } else if (z == 1) {
        gemm_body<0,0,0,1>(gqk, wk, bk, nullptr, ok, 768, 768);
    } else {
        gemm_body<0,0,0,1>(gqk, wq, bq, nullptr, oq, 768, 768);
    }
}

// ---------------- fused double conv for F=7 stage (order=2), exact fp32
#define C7_SMEM ((76*68 + 70*16 + 70*68)*4)
__global__ void __launch_bounds__(256) conv7_fused(
    const float* __restrict__ h, const float* __restrict__ p,
    float* __restrict__ out)
{
    extern __shared__ float csm[];
    float* hs = csm;                 // 76 x 68  (rows: t0-12 .. t0+63)
    float* ps = csm + 76*68;         // 70 x 16  (rows: t0-6 .. t0+63, 14 taps)
    float* h1 = csm + 76*68 + 70*16; // 70 x 68  (rows: t0-6 .. t0+63)
    const int tid = threadIdx.x;
    const int d0  = blockIdx.x * 64;
    const int bt0 = blockIdx.y * 64;
    const int batch = bt0 / Lq;
    const int t0    = bt0 & (Lq - 1);

    for (int idx = tid; idx < 76*16; idx += 256) {
        int row = idx >> 4, c4 = (idx & 15) * 4;
        int lt = t0 - 12 + row;
        float4 v = make_float4(0.f, 0.f, 0.f, 0.f);
        if (lt >= 0)
            v = *(const float4*)(h + (size_t)(batch*Lq + lt) * Dq + d0 + c4);
        *(float4*)&hs[row*68 + c4] = v;
    }
    for (int idx = tid; idx < 70*14; idx += 256) {
        int row = idx / 14, c = idx % 14;
        int lt = t0 - 6 + row;
        int gbt = batch*Lq + (lt >= 0 ? lt : 0);
        ps[row*16 + c] = p[(size_t)gbt * 14 + c];
    }
    __syncthreads();

    for (int idx = tid; idx < 70*16; idx += 256) {
        int row = idx >> 4, c4 = (idx & 15) * 4;
        float ax = 0.f, ay = 0.f, az = 0.f, aw = 0.f;
        #pragma unroll
        for (int m = 6; m >= 0; --m) {
            float kv = ps[row*16 + m];
            const float4 hv = *(const float4*)&hs[(row + 6 - m)*68 + c4];
            ax = fmaf(kv, hv.x, ax);
            ay = fmaf(kv, hv.y, ay);
            az = fmaf(kv, hv.z, az);
            aw = fmaf(kv, hv.w, aw);
        }
        float4 o;
        o.x = gelu_f(ax); o.y = gelu_f(ay); o.z = gelu_f(az); o.w = gelu_f(aw);
        *(float4*)&h1[row*68 + c4] = o;
    }
    __syncthreads();

    for (int idx = tid; idx < 64*16; idx += 256) {
        int row = idx >> 4, c4 = (idx & 15) * 4;
        float ax = 0.f, ay = 0.f, az = 0.f, aw = 0.f;
        #pragma unroll
        for (int m = 6; m >= 0; --m) {
            float kv = ps[(row + 6)*16 + 7 + m];
            const float4 hv = *(const float4*)&h1[(row + 6 - m)*68 + c4];
            ax = fmaf(kv, hv.x, ax);
            ay = fmaf(kv, hv.y, ay);
            az = fmaf(kv, hv.z, az);
            aw = fmaf(kv, hv.w, aw);
        }
        float4 o;
        o.x = gelu_f(ax); o.y = gelu_f(ay); o.z = gelu_f(az); o.w = gelu_f(aw);
        *(float4*)(out + (size_t)(bt0 + row) * Dq + d0 + c4) = o;
    }
}

// ---------------- smem-tiled conv + GELU, register sliding window
#define CONV_SMEM ((128*68 + 64*68)*4)
template<int F>
__global__ void __launch_bounds__(256) conv_tiled(
    const float* __restrict__ h, const float* __restrict__ p,
    float* __restrict__ out, int pstride, int poff)
{
    extern __shared__ float csm[];
    float* hs = csm;            // 128 x 68
    float* ps = csm + 128*68;   // 64 x 68
    const int tid = threadIdx.x;
    const int d0  = blockIdx.x * 64;
    const int bt0 = blockIdx.y * 64;
    const int batch = bt0 / Lq;
    const int t0    = bt0 & (Lq - 1);
    const int tg = tid >> 4;
    const int dg = tid & 15;

    float4 acc[4];
    #pragma unroll
    for (int i = 0; i < 4; i++) acc[i] = make_float4(0.f, 0.f, 0.f, 0.f);

    for (int m0 = F - 64; m0 >= 0; m0 -= 64) {
        if (m0 != F - 64) __syncthreads();
        for (int idx = tid; idx < 128*16; idx += 256) {
            int row = idx >> 4, c4 = (idx & 15) * 4;
            int lt = t0 - m0 - 64 + row;
            float4 v = make_float4(0.f, 0.f, 0.f, 0.f);
            if (lt >= 0)
                v = *(const float4*)(h + (size_t)(batch*Lq + lt) * Dq + d0 + c4);
            *(float4*)&hs[row*68 + c4] = v;
        }
        for (int idx = tid; idx < 64*16; idx += 256) {
            int row = idx >> 4, c4 = (idx & 15) * 4;
            float4 v = *(const float4*)(p + (size_t)(bt0 + row) * pstride + poff + m0 + c4);
            *(float4*)&ps[row*68 + c4] = v;
        }
        __syncthreads();

        float4 win[4];
        #pragma unroll
        for (int j = 0; j < 4; j++)
            win[j] = *(const float4*)&hs[(tg*4 + 1 + j)*68 + dg*4];

        #pragma unroll
        for (int grp = 15; grp >= 0; --grp) {
            float pka[4][4];
            #pragma unroll
            for (int i = 0; i < 4; i++)
                *(float4*)pka[i] = *(const float4*)&ps[(tg*4 + i)*68 + grp*4];
            #pragma unroll
            for (int u = 3; u >= 0; --u) {
                const int mi = grp*4 + u;
                #pragma unroll
                for (int i = 0; i < 4; i++) {
                    float pk = pka[i][u];
                    acc[i].x = fmaf(pk, win[i].x, acc[i].x);
                    acc[i].y = fmaf(pk, win[i].y, acc[i].y);
                    acc[i].z = fmaf(pk, win[i].z, acc[i].z);
                    acc[i].w = fmaf(pk, win[i].w, acc[i].w);
                }
                if (mi > 0) {
                    win[0] = win[1]; win[1] = win[2]; win[2] = win[3];
                    win[3] = *(const float4*)&hs[(tg*4 + 68 - mi)*68 + dg*4];
                }
            }
        }
    }

    #pragma unroll
    for (int i = 0; i < 4; i++) {
        float4 o;
        o.x = gelu_f(acc[i].x); o.y = gelu_f(acc[i].y);
        o.z = gelu_f(acc[i].z); o.w = gelu_f(acc[i].w);
        *(float4*)(out + (size_t)(bt0 + tg*4 + i) * Dq + d0 + dg*4) = o;
    }
}

// ---------------- LayerNorm of (a+b): two-pass, fp64 accumulators
__global__ void ln_kernel(const float* __restrict__ a, const float* __restrict__ b,
                          const float* __restrict__ g, const float* __restrict__ be,
                          float* __restrict__ out)
{
    __shared__ double red[10];
    int row = blockIdx.x, tid = threadIdx.x;
    const float* pa = a + (size_t)row * Dq;
    const float* pb = b + (size_t)row * Dq;
    float v[3];
    double s = 0.0;
    #pragma unroll
    for (int i = 0; i < 3; i++) {
        float x = pa[tid + 256*i] + pb[tid + 256*i];
        v[i] = x; s += (double)x;
    }
    #pragma unroll
    for (int o = 16; o; o >>= 1) s += __shfl_down_sync(0xffffffffu, s, o);
    if ((tid & 31) == 0) red[tid >> 5] = s;
    __syncthreads();
    if (tid == 0) {
        double t = 0.0;
        #pragma unroll
        for (int w = 0; w < 8; w++) t += red[w];
        red[8] = t * (1.0/768.0);
    }
    __syncthreads();
    float mean = (float)red[8];

    double s2 = 0.0;
    #pragma unroll
    for (int i = 0; i < 3; i++) {
        double d = (double)v[i] - red[8];
        s2 += d * d;
    }
    #pragma unroll
    for (int o = 16; o; o >>= 1) s2 += __shfl_down_sync(0xffffffffu, s2, o);
    if ((tid & 31) == 0) red[tid >> 5] = s2;
    __syncthreads();
    if (tid == 0) {
        double t = 0.0;
        #pragma unroll
        for (int w = 0; w < 8; w++) t += red[w];
        red[9] = 1.0 / sqrt(t * (1.0/768.0) + 1e-5);
    }
    __syncthreads();
    float rs = (float)red[9];
    #pragma unroll
    for (int i = 0; i < 3; i++) {
        int c = tid + 256*i;
        out[(size_t)row * Dq + c] = (v[i] - mean) * rs * g[c] + be[c];
    }
}

// ---------------- fused LayerNorm(a+b) + RoPE
__global__ void ln_rope_kernel(const float* __restrict__ a, const float* __restrict__ b,
                               const float* __restrict__ g, const float* __restrict__ be,
                               const float* __restrict__ sn, const float* __restrict__ cs,
                               float* __restrict__ ox, float* __restrict__ oqk)
{
    __shared__ double red[10];
    __shared__ float srow[768];
    int row = blockIdx.x, tid = threadIdx.x;
    int l = row & (Lq - 1);
    const float* pa = a + (size_t)row * Dq;
    const float* pb = b + (size_t)row * Dq;
    float v[3];
    double s = 0.0;
    #pragma unroll
    for (int i = 0; i < 3; i++) {
        float x = pa[tid + 256*i] + pb[tid + 256*i];
        v[i] = x; s += (double)x;
    }
    #pragma unroll
    for (int o = 16; o; o >>= 1) s += __shfl_down_sync(0xffffffffu, s, o);
    if ((tid & 31) == 0) red[tid >> 5] = s;
    __syncthreads();
    if (tid == 0) {
        double t = 0.0;
        #pragma unroll
        for (int w = 0; w < 8; w++) t += red[w];
        red[8] = t * (1.0/768.0);
    }
    __syncthreads();
    float mean = (float)red[8];

    double s2 = 0.0;
    #pragma unroll
    for (int i = 0; i < 3; i++) {
        double d = (double)v[i] - red[8];
        s2 += d * d;
    }
    #pragma unroll
    for (int o = 16; o; o >>= 1) s2 += __shfl_down_sync(0xffffffffu, s2, o);
    if ((tid & 31) == 0) red[tid >> 5] = s2;
    __syncthreads();
    if (tid == 0) {
        double t = 0.0;
        #pragma unroll
        for (int w = 0; w < 8; w++) t += red[w];
        red[9] = 1.0 / sqrt(t * (1.0/768.0) + 1e-5);
    }
    __syncthreads();
    float rs = (float)red[9];
    #pragma unroll
    for (int i = 0; i < 3; i++) {
        int c = tid + 256*i;
        float y = (v[i] - mean) * rs * g[c] + be[c];
        ox[(size_t)row * Dq + c] = y;
        srow[c] = y;
    }
    __syncthreads();
    #pragma unroll
    for (int i = 0; i < 3; i++) {
        int c = tid + 256*i;
        float r;
        if (c < 384) {
            float sv = sn[l*384 + c], cv = cs[l*384 + c];
            r = srow[c] * cv - srow[c + 384] * sv;
        } else {
            int d = c - 384;
            float sv = sn[l*384 + d], cv = cs[l*384 + d];
            r = srow[c] * cv + srow[d] * sv;
        }
        oqk[(size_t)row * Dq + c] = tf32r(r);
    }
}

// ---------------- tensor-core flash attention, hd=64; 64-query tiles, 128 thr,
// Q fragments in registers, 3 blocks/SM
#define ATS 68
#define VTS 72
#define PS  68
#define ATT_SMEM ((64*ATS + 64*VTS + 64*PS)*4)
__global__ void __launch_bounds__(128, 3) attn_mma(
    const float* __restrict__ Q, const float* __restrict__ K,
    const float* __restrict__ V, float* __restrict__ O)
{
    extern __shared__ float sm[];
    float* Ks = sm;
    float* Vs = sm + 64*ATS;
    float* Ps = sm + 64*ATS + 64*VTS;
    const int tid = threadIdx.x;
    const int warp = tid >> 5, lane = tid & 31;
    const int g = lane >> 2, tc = lane & 3;
    const int bh = blockIdx.y;
    const int b = bh / Hq, h = bh % Hq;
    const int q0 = blockIdx.x * 64;
    const size_t base = (size_t)b * Lq * Dq + (size_t)h * 64;
    const int rlo = warp*16 + g;

    uint32_t qa[8][4];
    {
        const float* qr0 = Q + base + (size_t)(q0 + rlo) * Dq;
        const float* qr1 = Q + base + (size_t)(q0 + rlo + 8) * Dq;
        #pragma unroll
        for (int i = 0; i < 8; i++) {
            int k8 = i * 8;
            qa[i][0] = __float_as_uint(qr0[k8 + tc]);
            qa[i][1] = __float_as_uint(qr1[k8 + tc]);
            qa[i][2] = __float_as_uint(qr0[k8 + tc + 4]);
            qa[i][3] = __float_as_uint(qr1[k8 + tc + 4]);
        }
    }

    float m0r = -INFINITY, m1r = -INFINITY, l0 = 0.f, l1 = 0.f;
    float o[8][4];
    #pragma unroll
    for (int ni = 0; ni < 8; ni++)
        #pragma unroll
        for (int j = 0; j < 4; j++) o[ni][j] = 0.f;

    for (int kt = 0; kt < Lq/64; ++kt) {
        __syncthreads();
        for (int i = tid; i < 64*16; i += 128) {
            int rr = i >> 4, c4 = (i & 15) * 4;
            *(float4*)&Ks[rr*ATS + c4] = *(const float4*)(K + base + (size_t)(kt*64 + rr) * Dq + c4);
            *(float4*)&Vs[rr*VTS + c4] = *(const float4*)(V + base + (size_t)(kt*64 + rr) * Dq + c4);
        }
        __syncthreads();

        float s[8][4];
        #pragma unroll
        for (int ni = 0; ni < 8; ni++)
            #pragma unroll
            for (int j = 0; j < 4; j++) s[ni][j] = 0.f;
        #pragma unroll
        for (int i8 = 0; i8 < 8; i8++) {
            const int k8 = i8 * 8;
            #pragma unroll
            for (int ni = 0; ni < 8; ni++) {
                uint32_t b0 = __float_as_uint(Ks[(ni*8 + g)*ATS + k8 + tc]);
                uint32_t b1 = __float_as_uint(Ks[(ni*8 + g)*ATS + k8 + tc + 4]);
                asm volatile(
                    "mma.sync.aligned.m16n8k8.row.col.f32.tf32.tf32.f32 "
                    "{%0,%1,%2,%3}, {%4,%5,%6,%7}, {%8,%9}, {%0,%1,%2,%3};"
                    : "+f"(s[ni][0]), "+f"(s[ni][1]), "+f"(s[ni][2]), "+f"(s[ni][3])
                    : "r"(qa[i8][0]), "r"(qa[i8][1]), "r"(qa[i8][2]), "r"(qa[i8][3]),
                      "r"(b0), "r"(b1));
            }
        }
        #pragma unroll
        for (int ni = 0; ni < 8; ni++)
            #pragma unroll
            for (int j = 0; j < 4; j++) s[ni][j] *= 0.125f;

        float mx0 = -INFINITY, mx1 = -INFINITY;
        #pragma unroll
        for (int ni = 0; ni < 8; ni++) {
            mx0 = fmaxf(mx0, fmaxf(s[ni][0], s[ni][1]));
            mx1 = fmaxf(mx1, fmaxf(s[ni][2], s[ni][3]));
        }
        mx0 = fmaxf(mx0, __shfl_xor_sync(0xffffffffu, mx0, 1));
        mx0 = fmaxf(mx0, __shfl_xor_sync(0xffffffffu, mx0, 2));
        mx1 = fmaxf(mx1, __shfl_xor_sync(0xffffffffu, mx1, 1));
        mx1 = fmaxf(mx1, __shfl_xor_sync(0xffffffffu, mx1, 2));
        float mn0 = fmaxf(m0r, mx0), mn1 = fmaxf(m1r, mx1);
        float ps0 = 0.f, ps1 = 0.f;
        #pragma unroll
        for (int ni = 0; ni < 8; ni++) {
            s[ni][0] = __expf(s[ni][0] - mn0); ps0 += s[ni][0];
            s[ni][1] = __expf(s[ni][1] - mn0); ps0 += s[ni][1];
            s[ni][2] = __expf(s[ni][2] - mn1); ps1 += s[ni][2];
            s[ni][3] = __expf(s[ni][3] - mn1); ps1 += s[ni][3];
        }
        ps0 += __shfl_xor_sync(0xffffffffu, ps0, 1);
        ps0 += __shfl_xor_sync(0xffffffffu, ps0, 2);
        ps1 += __shfl_xor_sync(0xffffffffu, ps1, 1);
        ps1 += __shfl_xor_sync(0xffffffffu, ps1, 2);
        float al0 = __expf(m0r - mn0), al1 = __expf(m1r - mn1);
        l0 = l0 * al0 + ps0;  m0r = mn0;
        l1 = l1 * al1 + ps1;  m1r = mn1;
        #pragma unroll
        for (int ni = 0; ni < 8; ni++) {
            o[ni][0] *= al0; o[ni][1] *= al0;
            o[ni][2] *= al1; o[ni][3] *= al1;
        }

        #pragma unroll
        for (int ni = 0; ni < 8; ni++) {
            *(float2*)&Ps[rlo*PS + ni*8 + 2*tc] =
                make_float2(tf32r(s[ni][0]), tf32r(s[ni][1]));
            *(float2*)&Ps[(rlo+8)*PS + ni*8 + 2*tc] =
                make_float2(tf32r(s[ni][2]), tf32r(s[ni][3]));
        }
        __syncwarp();

        #pragma unroll
        for (int k8 = 0; k8 < 64; k8 += 8) {
            uint32_t a0 = __float_as_uint(Ps[(warp*16 + g)*PS + k8 + tc]);
            uint32_t a1 = __float_as_uint(Ps[(warp*16 + g + 8)*PS + k8 + tc]);
            uint32_t a2 = __float_as_uint(Ps[(warp*16 + g)*PS + k8 + tc + 4]);
            uint32_t a3 = __float_as_uint(Ps[(warp*16 + g + 8)*PS + k8 + tc + 4]);
            #pragma unroll
            for (int ni = 0; ni < 8; ni++) {
                uint32_t b0 = __float_as_uint(Vs[(k8 + tc)*VTS + ni*8 + g]);
                uint32_t b1 = __float_as_uint(Vs[(k8 + tc + 4)*VTS + ni*8 + g]);
                asm volatile(
                    "mma.sync.aligned.m16n8k8.row.col.f32.tf32.tf32.f32 "
                    "{%0,%1,%2,%3}, {%4,%5,%6,%7}, {%8,%9}, {%0,%1,%2,%3};"
                    : "+f"(o[ni][0]), "+f"(o[ni][1]), "+f"(o[ni][2]), "+f"(o[ni][3])
                    : "r"(a0), "r"(a1), "r"(a2), "r"(a3), "r"(b0), "r"(b1));
            }
        }
    }

    float inv0 = 1.f / l0, inv1 = 1.f / l1;
    #pragma unroll
    for (int ni = 0; ni < 8; ni++) {
        *(float2*)(O + base + (size_t)(q0 + rlo) * Dq + ni*8 + 2*tc) =
            make_float2(tf32r(o[ni][0]*inv0), tf32r(o[ni][1]*inv0));
        *(float2*)(O + base + (size_t)(q0 + rlo + 8) * Dq + ni*8 + 2*tc) =
            make_float2(tf32r(o[ni][2]*inv1), tf32r(o[ni][3]*inv1));
    }
}

// ---------------- host orchestration ----------------
extern "C" void kernel_launch(void* const* d_in, const int* in_sizes, int n_in,
                              void* d_out, int out_size)
{
    (void)n_in; (void)out_size;
    const float* x   = (const float*)d_in[0];
    const float* sn  = (const float*)d_in[1];
    const float* cs  = (const float*)d_in[2];
    const float* w1s[3] = {(const float*)d_in[3], (const float*)d_in[7],  (const float*)d_in[11]};
    const float* b1s[3] = {(const float*)d_in[4], (const float*)d_in[8],  (const float*)d_in[12]};
    const float* w2s[3] = {(const float*)d_in[5], (const float*)d_in[9],  (const float*)d_in[13]};
    const float* b2s[3] = {(const float*)d_in[6], (const float*)d_in[10], (const float*)d_in[14]};
    const float* ln1g = (const float*)d_in[15];
    const float* ln1b = (const float*)d_in[16];
    const float* ln2g = (const float*)d_in[17];
    const float* ln2b = (const float*)d_in[18];

    const float *wq, *bqv, *wk, *bkv, *wv, *bvv, *wo, *bov;
    if (in_sizes[20] == 768) {
        wq = (const float*)d_in[19]; bqv = (const float*)d_in[20];
        wk = (const float*)d_in[21]; bkv = (const float*)d_in[22];
        wv = (const float*)d_in[23]; bvv = (const float*)d_in[24];
        wo = (const float*)d_in[25]; bov = (const float*)d_in[26];
    } else {
        wq = (const float*)d_in[19]; wk  = (const float*)d_in[20];
        wv = (const float*)d_in[21]; wo  = (const float*)d_in[22];
        bqv = (const float*)d_in[23]; bkv = (const float*)d_in[24];
        bvv = (const float*)d_in[25]; bov = (const float*)d_in[26];
    }
    const float* mw1 = (const float*)d_in[27]; const float* mb1 = (const float*)d_in[28];
    const float* mw2 = (const float*)d_in[29]; const float* mb2 = (const float*)d_in[30];

    float *t1, *pp, *ha, *hb, *gx, *gqk, *gq, *gk, *gv, *gatt, *go, *gx2, *wr;
    cudaGetSymbolAddress((void**)&t1,  g_t1);
    cudaGetSymbolAddress((void**)&pp,  g_p);
    cudaGetSymbolAddress((void**)&ha,  g_ha);
    cudaGetSymbolAddress((void**)&hb,  g_hb);
    cudaGetSymbolAddress((void**)&gx,  g_x);
    cudaGetSymbolAddress((void**)&gqk, g_qk);
    cudaGetSymbolAddress((void**)&gq,  g_q);
    cudaGetSymbolAddress((void**)&gk,  g_k);
    cudaGetSymbolAddress((void**)&gv,  g_v);
    cudaGetSymbolAddress((void**)&gatt,g_att);
    cudaGetSymbolAddress((void**)&go,  g_o);
    cudaGetSymbolAddress((void**)&gx2, g_x2);
    cudaGetSymbolAddress((void**)&wr,  g_wr);

    WSrc ws;
    ws.s[0] = (const float4*)w1s[0]; ws.s[1] = (const float4*)w1s[1];
    ws.s[2] = (const float4*)w1s[2]; ws.s[3] = (const float4*)w2s[0];
    ws.s[4] = (const float4*)w2s[1]; ws.s[5] = (const float4*)w2s[2];
    ws.s[6] = (const float4*)wq;     ws.s[7] = (const float4*)wk;
    ws.s[8] = (const float4*)wv;     ws.s[9] = (const float4*)wo;
    ws.s[10] = (const float4*)mw1;   ws.s[11] = (const float4*)mw2;
    round_all<<<(W_TOTAL4 + 255)/256, 256>>>(ws, (float4*)wr);

    const float* rw1[3] = {wr, wr + 2359296, wr + 4718592};
    const float* rw2[3] = {wr + 7077888, wr + 7120896, wr + 8300544};
    const float *rwq = wr + 11446272, *rwk = wr + 12036096;
    const float *rwv = wr + 12625920, *rwo = wr + 13215744;
    const float *rmw1 = wr + 13805568, *rmw2 = wr + 16164864;

    cudaFuncSetAttribute(gemm_tc<1,0,1,1>, cudaFuncAttributeMaxDynamicSharedMemorySize, GEMM_SMEM);
    cudaFuncSetAttribute(gemm_tc<0,0,0,0>, cudaFuncAttributeMaxDynamicSharedMemorySize, GEMM_SMEM);
    cudaFuncSetAttribute(gemm_tc_sk<0>,    cudaFuncAttributeMaxDynamicSharedMemorySize, GEMM_SMEM);
    cudaFuncSetAttribute(gemm_tc_sk<1>,    cudaFuncAttributeMaxDynamicSharedMemorySize, GEMM_SMEM);
    cudaFuncSetAttribute(gemm_qkv,         cudaFuncAttributeMaxDynamicSharedMemorySize, GEMM_SMEM);
    cudaFuncSetAttribute(conv7_fused,      cudaFuncAttributeMaxDynamicSharedMemorySize, C7_SMEM);
    cudaFuncSetAttribute(conv_tiled<128>,  cudaFuncAttributeMaxDynamicSharedMemorySize, CONV_SMEM);
    cudaFuncSetAttribute(conv_tiled<256>,  cudaFuncAttributeMaxDynamicSharedMemorySize, CONV_SMEM);
    cudaFuncSetAttribute(attn_mma,         cudaFuncAttributeMaxDynamicSharedMemorySize, ATT_SMEM);

    const int orderF[3] = {14, 384, 1024};
    const int Fs[3]     = {7, 128, 256};
    const int ords[3]   = {2, 3, 4};
    const int skS[3]    = {8, 4, 2};
    const int skKC[3]   = {384, 768, 1536};

    const float* hcur = x;
    float* bufs[2] = {ha, hb};
    int cur = 0;

    for (int s3 = 0; s3 < 3; s3++) {
        gemm_tc<1,0,1,1><<<dim3(24,32), 256, GEMM_SMEM>>>(hcur, rw1[s3], b1s[s3], nullptr, t1, 3072, 768);
        cudaMemsetAsync(pp, 0, sizeof(float)*(size_t)ROWS*orderF[s3]);
        gemm_tc_sk<0><<<dim3((orderF[s3]+127)/128, 32, skS[s3]), 256, GEMM_SMEM>>>(
            t1, rw2[s3], b2s[s3], nullptr, pp, orderF[s3], 3072, skKC[s3]);
        if (Fs[s3] == 7) {
            conv7_fused<<<dim3(12,64), 256, C7_SMEM>>>(hcur, pp, bufs[cur]);
            hcur = bufs[cur];
            cur ^= 1;
        } else {
            for (int i = 0; i < ords[s3]; i++) {
                if (Fs[s3] == 128)
                    conv_tiled<128><<<dim3(12,64), 256, CONV_SMEM>>>(hcur, pp, bufs[cur], orderF[s3], i * 128);
                else
                    conv_tiled<256><<<dim3(12,64), 256, CONV_SMEM>>>(hcur, pp, bufs[cur], orderF[s3], i * 256);
                hcur = bufs[cur];
                cur ^= 1;
            }
        }
    }

    ln_rope_kernel<<<ROWS, 256>>>(x, hcur, ln1g, ln1b, sn, cs, gx, gqk);

    gemm_qkv<<<dim3(6,32,3), 256, GEMM_SMEM>>>(gqk, gx, rwq, bqv, gq, rwk, bkv, gk, rwv, bvv, gv);

    attn_mma<<<dim3(Lq/64, Bq*Hq), 128, ATT_SMEM>>>(gq, gk, gv, gatt);

    cudaMemsetAsync(go, 0, sizeof(float)*(size_t)ROWS*768);
    gemm_tc_sk<0><<<dim3(6,32,2), 256, GEMM_SMEM>>>(
        gatt, rwo, bov, nullptr, go, 768, 768, 384);

    ln_kernel<<<ROWS, 256>>>(gx, go, ln2g, ln2b, gx2);
    gemm_tc<1,0,1,1><<<dim3(24,32), 256, GEMM_SMEM>>>(gx2, rmw1, mb1, nullptr, t1, 3072, 768);
    cudaMemsetAsync(d_out, 0, sizeof(float)*(size_t)ROWS*768);
    gemm_tc_sk<1><<<dim3(6,32,2), 256, GEMM_SMEM>>>(
        t1, rmw2, mb2, gx2, (float*)d_out, 768, 3072, 1536);
}